// round 6
// baseline (speedup 1.0000x reference)
#include <cuda_runtime.h>
#include <cstdint>

#define NP 100000
#define NA 50000
#define H  128
#define EC_MAX 1000000
#define EW_MAX 320000

// ---------------- device scratch ----------------
__device__ float g_acc_c[(size_t)NP * H];
__device__ float g_acc_w[(size_t)NP * H];
__device__ float g_acc_r[(size_t)NA * H];
__device__ float g_Oc[(size_t)NP * H];          // scaled cites output (0.5*O/||O||)
__device__ float g_xp[(size_t)NP * H];
__device__ float g_xa[(size_t)NA * H];
__device__ float g_Bf[6][65536];                // fragment-major weights (hi+lo)
// CSR
__device__ int g_cnt_c[NP], g_cnt_w[NP], g_cnt_r[NA];
__device__ int g_rp_c[NP], g_rp_w[NP], g_rp_r[NA];
__device__ int g_cur_c[NP], g_cur_w[NP], g_cur_r[NA];
__device__ int g_col_c[EC_MAX], g_col_w[EW_MAX], g_col_r[EW_MAX];
__device__ int g_total[3];

// ---------------- helpers ----------------
__device__ __forceinline__ uint32_t f2tf_u(float f) {
    uint32_t r;
    asm("cvt.rna.tf32.f32 %0, %1;" : "=r"(r) : "f"(f));
    return r;
}
__device__ __forceinline__ float f2tf_f(float f) { return __uint_as_float(f2tf_u(f)); }

// ---------------- CSR build ----------------
__global__ void counti_kernel(const int* __restrict__ dst, int* __restrict__ cnt, int nE) {
    int e = blockIdx.x * blockDim.x + threadIdx.x;
    if (e < nE) atomicAdd(&cnt[dst[e]], 1);
}

__global__ void assign_kernel(const int* __restrict__ cnt, int* __restrict__ rp,
                              int* __restrict__ cur, int* __restrict__ total, int n) {
    int i = blockIdx.x * blockDim.x + threadIdx.x;
    int lane = threadIdx.x & 31;
    int v = (i < n) ? cnt[i] : 0;
    int incl = v;
#pragma unroll
    for (int o = 1; o < 32; o <<= 1) {
        int t = __shfl_up_sync(0xffffffffu, incl, o);
        if (lane >= o) incl += t;
    }
    int wsum = __shfl_sync(0xffffffffu, incl, 31);
    int base = 0;
    if (lane == 31) base = atomicAdd(total, wsum);
    base = __shfl_sync(0xffffffffu, base, 31);
    int off = base + incl - v;
    if (i < n) { rp[i] = off; cur[i] = off; }
}

__global__ void fill_kernel(const int* __restrict__ src, const int* __restrict__ dst,
                            int* __restrict__ cur, int* __restrict__ col, int nE) {
    int e = blockIdx.x * blockDim.x + threadIdx.x;
    if (e < nE) {
        int d = dst[e];
        int p = atomicAdd(&cur[d], 1);
        col[p] = src[e];
    }
}

// ---------------- gather-mean aggregation: warp per dst node ----------------
__global__ void aggregate_kernel(const float* __restrict__ x, const int* __restrict__ rp,
                                 const int* __restrict__ cnt, const int* __restrict__ col,
                                 float* __restrict__ acc, int n) {
    int gw   = (blockIdx.x * blockDim.x + threadIdx.x) >> 5;
    int lane = threadIdx.x & 31;
    if (gw >= n) return;
    const int beg = __ldg(&rp[gw]);
    const int deg = __ldg(&cnt[gw]);
    const int end = beg + deg;
    float4 s = make_float4(0.f, 0.f, 0.f, 0.f);
    for (int b = beg; b < end; b += 32) {
        int nb = min(32, end - b);
        int my = (b + lane < end) ? __ldg(&col[b + lane]) : 0;
        for (int j = 0; j < nb; j++) {
            int sn = __shfl_sync(0xffffffffu, my, j);
            float4 v = *(const float4*)(x + (size_t)sn * H + lane * 4);
            s.x += v.x; s.y += v.y; s.z += v.z; s.w += v.w;
        }
    }
    float inv = 1.0f / fmaxf((float)deg, 1.0f);
    s.x *= inv; s.y *= inv; s.z *= inv; s.w *= inv;
    *(float4*)(acc + (size_t)gw * H + lane * 4) = s;
}

// ---------------- fragment-major weight prep ----------------
// For g(0..31: K-steps of 8), wn(0..1), mat(0:hi,1:lo): block of 512 floats.
// Within block: j(0..3), lane-perm (cq*8+rq)*4 + e; e -> nt=2j+(e>>1), b=e&1.
// value(mat) with k = g*8+cq+b*4, col = wn*64+nt*8+rq, source Wl (k<128) else Wr.
__global__ void prep_bf(const float* __restrict__ Wl, const float* __restrict__ Wr,
                        float* __restrict__ Bf) {
    int i = blockIdx.x * blockDim.x + threadIdx.x;   // 65536
    if (i >= 65536) return;
    int blk = i >> 9;
    int mat = blk & 1, wn = (blk >> 1) & 1, g = blk >> 2;
    int o = i & 511;
    int j = o >> 7;
    int r7 = (o >> 2) & 31;
    int cq = r7 >> 3, rq = r7 & 7;
    int e = o & 3;
    int nt = 2 * j + (e >> 1);
    int b = e & 1;
    int k = g * 8 + cq + b * 4;
    int col = wn * 64 + nt * 8 + rq;
    float w = (k < 128) ? Wl[k * 128 + col] : Wr[(k - 128) * 128 + col];
    float h = f2tf_f(w);
    Bf[i] = mat ? f2tf_f(w - h) : h;
}

// ---------------- fused tf32 GEMM + normalize epilogue ----------------
// MODE 0: out = (O)*0.5/||O||            (cites -> Oc buffer, no relu)
// MODE 1: out = relu(prev + O*0.5/||O||) (writes -> final paper)
// MODE 2: out = relu(O/||O||)            (rev -> final author)
template <int MODE>
__global__ void __launch_bounds__(256, 2) sage_gemm_fused(
    const float* __restrict__ acc, const float* __restrict__ xdst,
    const float* __restrict__ Bf, const float* __restrict__ bias,
    const float* __restrict__ prev, float* __restrict__ out, int n)
{
    __shared__ float bs[128];
    __shared__ float As[128 * 36];
    __shared__ float rowsq[256];

    const int tid  = threadIdx.x;
    const int lane = tid & 31;
    const int wid  = tid >> 5;
    const int wm   = wid & 3;
    const int wn   = wid >> 2;
    const int row0 = blockIdx.x * 128;
    const int rq   = lane >> 2;
    const int cq   = lane & 3;

    if (tid < 128) bs[tid] = __ldg(&bias[tid]);
    __syncthreads();

    float c[2][8][4];
#pragma unroll
    for (int mt = 0; mt < 2; mt++)
#pragma unroll
        for (int nt = 0; nt < 8; nt++) {
            float b0 = bs[wn * 64 + nt * 8 + cq * 2];
            float b1 = bs[wn * 64 + nt * 8 + cq * 2 + 1];
            c[mt][nt][0] = b0; c[mt][nt][1] = b1;
            c[mt][nt][2] = b0; c[mt][nt][3] = b1;
        }

    const int tb = (cq * 8 + rq) * 4;   // B lane offset within 512-float block

    float4 areg[4];
    // prefetch chunk 0
#pragma unroll
    for (int l = 0; l < 4; l++) {
        int idx = tid + l * 256;
        int r = idx >> 3, klv = (idx & 7) << 2;
        int rg = row0 + r;
        areg[l] = make_float4(0.f, 0.f, 0.f, 0.f);
        if (rg < n) {
            areg[l] = (klv < 128)
                ? *(const float4*)(acc + (size_t)rg * H + klv)
                : *(const float4*)(xdst + (size_t)rg * H + (klv - 128));
        }
    }

    for (int ch = 0; ch < 8; ch++) {
        __syncthreads();   // previous chunk's As reads done
        // store prefetched A (convert to tf32)
#pragma unroll
        for (int l = 0; l < 4; l++) {
            int idx = tid + l * 256;
            int r = idx >> 3, klv = (idx & 7) << 2;
            float* p = As + r * 36 + klv;
            p[0] = f2tf_f(areg[l].x); p[1] = f2tf_f(areg[l].y);
            p[2] = f2tf_f(areg[l].z); p[3] = f2tf_f(areg[l].w);
        }
        // prefetch next chunk
        if (ch < 7) {
            const int kc = (ch + 1) * 32;
#pragma unroll
            for (int l = 0; l < 4; l++) {
                int idx = tid + l * 256;
                int r = idx >> 3, klv = (idx & 7) << 2;
                int rg = row0 + r;
                int kg = kc + klv;
                areg[l] = make_float4(0.f, 0.f, 0.f, 0.f);
                if (rg < n) {
                    areg[l] = (kg < 128)
                        ? *(const float4*)(acc + (size_t)rg * H + kg)
                        : *(const float4*)(xdst + (size_t)rg * H + (kg - 128));
                }
            }
        }
        __syncthreads();

#pragma unroll
        for (int ks = 0; ks < 4; ks++) {
            const int k0 = ks * 8;
            const int g = ch * 4 + ks;
            uint32_t au[2][4];
#pragma unroll
            for (int mt = 0; mt < 2; mt++) {
                const float* ap = As + (wm * 32 + mt * 16 + rq) * 36 + k0 + cq;
                au[mt][0] = __float_as_uint(ap[0]);
                au[mt][1] = __float_as_uint(ap[8 * 36]);
                au[mt][2] = __float_as_uint(ap[4]);
                au[mt][3] = __float_as_uint(ap[8 * 36 + 4]);
            }
#pragma unroll
            for (int mat = 0; mat < 2; mat++) {
                const float* bp = Bf + ((((g * 2 + wn) * 2 + mat)) << 9) + tb;
#pragma unroll
                for (int j = 0; j < 4; j++) {
                    float4 f = *(const float4*)(bp + j * 128);
                    uint32_t b0a = __float_as_uint(f.x), b1a = __float_as_uint(f.y);
                    uint32_t b0b = __float_as_uint(f.z), b1b = __float_as_uint(f.w);
                    const int nt0 = 2 * j, nt1 = 2 * j + 1;
#pragma unroll
                    for (int mt = 0; mt < 2; mt++) {
                        asm volatile(
                            "mma.sync.aligned.m16n8k8.row.col.f32.tf32.tf32.f32 "
                            "{%0, %1, %2, %3}, {%4, %5, %6, %7}, {%8, %9}, {%0, %1, %2, %3};"
                            : "+f"(c[mt][nt0][0]), "+f"(c[mt][nt0][1]),
                              "+f"(c[mt][nt0][2]), "+f"(c[mt][nt0][3])
                            : "r"(au[mt][0]), "r"(au[mt][1]), "r"(au[mt][2]), "r"(au[mt][3]),
                              "r"(b0a), "r"(b1a));
                        asm volatile(
                            "mma.sync.aligned.m16n8k8.row.col.f32.tf32.tf32.f32 "
                            "{%0, %1, %2, %3}, {%4, %5, %6, %7}, {%8, %9}, {%0, %1, %2, %3};"
                            : "+f"(c[mt][nt1][0]), "+f"(c[mt][nt1][1]),
                              "+f"(c[mt][nt1][2]), "+f"(c[mt][nt1][3])
                            : "r"(au[mt][0]), "r"(au[mt][1]), "r"(au[mt][2]), "r"(au[mt][3]),
                              "r"(b0b), "r"(b1b));
                    }
                }
            }
        }
    }

    // ---- epilogue: per-row L2 norm across both wn halves, then scale/combine ----
    __syncthreads();
#pragma unroll
    for (int mt = 0; mt < 2; mt++)
#pragma unroll
        for (int hm = 0; hm < 2; hm++) {
            float s = 0.f;
#pragma unroll
            for (int nt = 0; nt < 8; nt++) {
                float a = c[mt][nt][hm * 2], b = c[mt][nt][hm * 2 + 1];
                s += a * a + b * b;
            }
            s += __shfl_xor_sync(0xffffffffu, s, 1);
            s += __shfl_xor_sync(0xffffffffu, s, 2);
            if (cq == 0) rowsq[wn * 128 + wm * 32 + mt * 16 + hm * 8 + rq] = s;
        }
    __syncthreads();

    const float SC = (MODE == 2) ? 1.0f : 0.5f;
#pragma unroll
    for (int mt = 0; mt < 2; mt++)
#pragma unroll
        for (int hm = 0; hm < 2; hm++) {
            int rl = wm * 32 + mt * 16 + hm * 8 + rq;
            int rg = row0 + rl;
            float tot = rowsq[rl] + rowsq[128 + rl];
            float f = SC / fmaxf(sqrtf(tot), 1e-12f);
            if (rg < n) {
#pragma unroll
                for (int nt = 0; nt < 8; nt++) {
                    int col = wn * 64 + nt * 8 + cq * 2;
                    float v0 = c[mt][nt][hm * 2] * f;
                    float v1 = c[mt][nt][hm * 2 + 1] * f;
                    if (MODE == 1) {
                        float2 p = *(const float2*)(prev + (size_t)rg * H + col);
                        v0 = fmaxf(p.x + v0, 0.f);
                        v1 = fmaxf(p.y + v1, 0.f);
                    } else if (MODE == 2) {
                        v0 = fmaxf(v0, 0.f);
                        v1 = fmaxf(v1, 0.f);
                    }
                    *(float2*)(out + (size_t)rg * H + col) = make_float2(v0, v1);
                }
            }
        }
}

// ---------------- host launcher ----------------
extern "C" void kernel_launch(void* const* d_in, const int* in_sizes, int n_in,
                              void* d_out, int out_size) {
    const float* x_paper  = (const float*)d_in[0];
    const float* x_author = (const float*)d_in[1];
    const int* cs = (const int*)d_in[2];
    const int* cd = (const int*)d_in[3];
    const int* ws = (const int*)d_in[4];
    const int* wd = (const int*)d_in[5];
    const int* rs = (const int*)d_in[6];
    const int* rd = (const int*)d_in[7];
    const int EC = in_sizes[2];
    const int EW = in_sizes[4];
    const float* W[18];
    for (int i = 0; i < 18; i++) W[i] = (const float*)d_in[8 + i];

    float *acc_c, *acc_w, *acc_r, *Oc, *xp, *xa, *BfB;
    int *cnt_c, *cnt_w, *cnt_r, *rp_c, *rp_w, *rp_r, *cur_c, *cur_w, *cur_r;
    int *col_c, *col_w, *col_r, *total;
    cudaGetSymbolAddress((void**)&acc_c, g_acc_c);
    cudaGetSymbolAddress((void**)&acc_w, g_acc_w);
    cudaGetSymbolAddress((void**)&acc_r, g_acc_r);
    cudaGetSymbolAddress((void**)&Oc, g_Oc);
    cudaGetSymbolAddress((void**)&xp, g_xp);
    cudaGetSymbolAddress((void**)&xa, g_xa);
    cudaGetSymbolAddress((void**)&BfB, g_Bf);
    cudaGetSymbolAddress((void**)&cnt_c, g_cnt_c);
    cudaGetSymbolAddress((void**)&cnt_w, g_cnt_w);
    cudaGetSymbolAddress((void**)&cnt_r, g_cnt_r);
    cudaGetSymbolAddress((void**)&rp_c, g_rp_c);
    cudaGetSymbolAddress((void**)&rp_w, g_rp_w);
    cudaGetSymbolAddress((void**)&rp_r, g_rp_r);
    cudaGetSymbolAddress((void**)&cur_c, g_cur_c);
    cudaGetSymbolAddress((void**)&cur_w, g_cur_w);
    cudaGetSymbolAddress((void**)&cur_r, g_cur_r);
    cudaGetSymbolAddress((void**)&col_c, g_col_c);
    cudaGetSymbolAddress((void**)&col_w, g_col_w);
    cudaGetSymbolAddress((void**)&col_r, g_col_r);
    cudaGetSymbolAddress((void**)&total, g_total);

    // ---- CSR build ----
    cudaMemsetAsync(cnt_c, 0, NP * sizeof(int));
    cudaMemsetAsync(cnt_w, 0, NP * sizeof(int));
    cudaMemsetAsync(cnt_r, 0, NA * sizeof(int));
    cudaMemsetAsync(total, 0, 3 * sizeof(int));
    counti_kernel<<<(EC + 255) / 256, 256>>>(cd, cnt_c, EC);
    counti_kernel<<<(EW + 255) / 256, 256>>>(wd, cnt_w, EW);
    counti_kernel<<<(EW + 255) / 256, 256>>>(rd, cnt_r, EW);
    assign_kernel<<<(NP + 255) / 256, 256>>>(cnt_c, rp_c, cur_c, total + 0, NP);
    assign_kernel<<<(NP + 255) / 256, 256>>>(cnt_w, rp_w, cur_w, total + 1, NP);
    assign_kernel<<<(NA + 255) / 256, 256>>>(cnt_r, rp_r, cur_r, total + 2, NA);
    fill_kernel<<<(EC + 255) / 256, 256>>>(cs, cd, cur_c, col_c, EC);
    fill_kernel<<<(EW + 255) / 256, 256>>>(ws, wd, cur_w, col_w, EW);
    fill_kernel<<<(EW + 255) / 256, 256>>>(rs, rd, cur_r, col_r, EW);

    // ---- fragment-major split weights ----
    for (int l = 0; l < 2; l++)
        for (int t = 0; t < 3; t++) {
            const float* Wl = W[l * 9 + t * 3 + 0];
            const float* Wr = W[l * 9 + t * 3 + 2];
            prep_bf<<<256, 256>>>(Wl, Wr, BfB + (l * 3 + t) * 65536);
        }

    const float* xpl = x_paper;
    const float* xal = x_author;
    for (int l = 0; l < 2; l++) {
        aggregate_kernel<<<(NP * 32 + 255) / 256, 256>>>(xpl, rp_c, cnt_c, col_c, acc_c, NP);
        aggregate_kernel<<<(NP * 32 + 255) / 256, 256>>>(xal, rp_w, cnt_w, col_w, acc_w, NP);
        aggregate_kernel<<<(NA * 32 + 255) / 256, 256>>>(xpl, rp_r, cnt_r, col_r, acc_r, NA);

        const float* Bfc = BfB + (l * 3 + 0) * 65536;
        const float* Bfw = BfB + (l * 3 + 1) * 65536;
        const float* Bfr = BfB + (l * 3 + 2) * 65536;

        float* po = (l == 1) ? (float*)d_out : xp;
        float* ao = (l == 1) ? ((float*)d_out + (size_t)NP * H) : xa;

        sage_gemm_fused<0><<<(NP + 127) / 128, 256>>>(
            acc_c, xpl, Bfc, W[l * 9 + 1], nullptr, Oc, NP);
        sage_gemm_fused<1><<<(NP + 127) / 128, 256>>>(
            acc_w, xpl, Bfw, W[l * 9 + 4], Oc, po, NP);
        sage_gemm_fused<2><<<(NA + 127) / 128, 256>>>(
            acc_r, xal, Bfr, W[l * 9 + 7], nullptr, ao, NA);

        xpl = xp;
        xal = xa;
    }
    (void)n_in; (void)out_size; (void)x_author;
}